// round 6
// baseline (speedup 1.0000x reference)
#include <cuda_runtime.h>
#include <math.h>

// Problem constants
#define BB 64
#define NN 8732
#define CC 21
#define KCAND 200
#define MAXPC 20
#define MAXTOT 20
#define FULLM 0xffffffffu

#define CAP    512               // per-(b,c) candidate list capacity
#define COLTH  0.95703125f       // collect threshold, classes >= 1
#define COLTH0 0.93f             // collect threshold, class 0 (masked less often)

// Scratch (static device globals: allowed; no runtime allocation)
__device__ float4             g_boxes[BB * NN];
__device__ unsigned char      g_mask[BB * NN];
__device__ unsigned long long g_cand[(size_t)BB * CC * CAP];
__device__ int                g_cnt[BB * CC];
__device__ float              g_cls_scores[BB * CC * MAXPC];
__device__ float4             g_cls_boxes[BB * CC * MAXPC];

// ---------------------------------------------------------------------------
// Kernel 0: zero the per-(b,c) candidate counters (graph replays need this)
// ---------------------------------------------------------------------------
__global__ void init_kernel() {
    int i = blockIdx.x * blockDim.x + threadIdx.x;
    if (i < BB * CC) g_cnt[i] = 0;
}

// ---------------------------------------------------------------------------
// Hybrid bitonic sort of 512 u64 keys, descending. 256 threads; thread t owns
// elements 2t, 2t+1 in registers; j<=32 via shfl, j in {64,128,256} via smem.
// ---------------------------------------------------------------------------
__device__ __forceinline__ void sort512_desc(unsigned long long* sk, int t) {
    unsigned long long a = sk[2 * t], b = sk[2 * t + 1];
#pragma unroll
    for (int k = 2; k <= 512; k <<= 1) {
#pragma unroll
        for (int j = k >> 1; j >= 1; j >>= 1) {
            const bool desc = (((2 * t) & k) == 0);
            if (j == 1) {
                unsigned long long hi = a > b ? a : b;
                unsigned long long lo = a > b ? b : a;
                a = desc ? hi : lo;
                b = desc ? lo : hi;
            } else if (j <= 32) {
                const int  l     = j >> 1;
                const bool lower = ((t & l) == 0);
                const bool wmax  = (desc == lower);
                unsigned long long oa = __shfl_xor_sync(FULLM, a, l);
                unsigned long long ob = __shfl_xor_sync(FULLM, b, l);
                a = wmax ? (a > oa ? a : oa) : (a < oa ? a : oa);
                b = wmax ? (b > ob ? b : ob) : (b < ob ? b : ob);
            } else {
                __syncthreads();
                sk[2 * t]     = a;
                sk[2 * t + 1] = b;
                __syncthreads();
                unsigned long long oa = sk[(2 * t) ^ j];
                unsigned long long ob = sk[(2 * t + 1) ^ j];
                const bool lower = (((2 * t) & j) == 0);
                const bool wmax  = (desc == lower);
                a = wmax ? (a > oa ? a : oa) : (a < oa ? a : oa);
                b = wmax ? (b > ob ? b : ob) : (b < ob ? b : ob);
            }
        }
    }
    sk[2 * t]     = a;
    sk[2 * t + 1] = b;
}

// ---------------------------------------------------------------------------
// Kernel A: one thread per (b, n): decode box + argmax mask + candidate push.
// Scores live in registers; L1 coalesces the 84B-stride label reads.
// ---------------------------------------------------------------------------
__global__ __launch_bounds__(256) void decode_kernel(
        const float* __restrict__ deltas,
        const float* __restrict__ labels,
        const float* __restrict__ anchors) {
    const int idx = blockIdx.x * blockDim.x + threadIdx.x;
    if (idx >= BB * NN) return;
    const int b = idx / NN;
    const int n = idx - b * NN;

    // 21 scores into registers
    const float* lr = labels + (size_t)idx * CC;
    float sc[CC];
#pragma unroll
    for (int c = 0; c < CC; c++) sc[c] = __ldg(lr + c);

    // argmax (first-occurrence ties, like jnp.argmax)
    float best = sc[0];
    int   bi   = 0;
#pragma unroll
    for (int c = 1; c < CC; c++) {
        if (sc[c] > best) { best = sc[c]; bi = c; }
    }
    const bool masked = (bi != 0);
    g_mask[idx] = masked ? 1 : 0;

    // decode box
    float4 a = __ldg(((const float4*)anchors) + n);
    float4 d = __ldg(((const float4*)deltas) + idx);
    d.x *= 0.1f; d.y *= 0.1f; d.z *= 0.2f; d.w *= 0.2f;

    float ah  = a.z - a.x;
    float aw  = a.w - a.y;
    float acy = a.x + 0.5f * ah;
    float acx = a.y + 0.5f * aw;
    float cy  = d.x * ah + acy;
    float cx  = d.y * aw + acx;
    float h   = expf(d.z) * ah;
    float w   = expf(d.w) * aw;

    g_boxes[idx] = make_float4(cy - 0.5f * h, cx - 0.5f * w,
                               cy + 0.5f * h, cx + 0.5f * w);

    // Candidate push: per-class threshold chosen so every list that reaches
    // cnt >= 200 provably contains the exact top-200 (all entries >= th).
    if (masked) {
        const unsigned key_lo = (unsigned)(~(unsigned)n);
#pragma unroll
        for (int c = 0; c < CC; c++) {
            const float th = (c == 0) ? COLTH0 : COLTH;
            if (sc[c] >= th) {
                int p = atomicAdd(&g_cnt[b * CC + c], 1);
                if (p < CAP) {
                    g_cand[(size_t)(b * CC + c) * CAP + p] =
                        ((unsigned long long)__float_as_uint(sc[c]) << 32)
                        | key_lo;
                }
            }
        }
    }
}

// ---------------------------------------------------------------------------
// IoU, exactly mirroring the reference fp32 formula
// ---------------------------------------------------------------------------
__device__ __forceinline__ float iou_f(float4 A, float4 B2) {
    float areaA = (A.z - A.x) * (A.w - A.y);
    float areaB = (B2.z - B2.x) * (B2.w - B2.y);
    float ih = fminf(A.z, B2.z) - fmaxf(A.x, B2.x); ih = fmaxf(ih, 0.0f);
    float iw = fminf(A.w, B2.w) - fmaxf(A.y, B2.y); iw = fmaxf(iw, 0.0f);
    float inter = ih * iw;
    return inter / (areaA + areaB - inter + 1e-8f);
}

// ---------------------------------------------------------------------------
// Kernel B: per-(b,c) sort of prebuilt candidates + greedy NMS (single warp,
// smem boxes) + first-20 output. One block (256 threads) per (b,c).
// ---------------------------------------------------------------------------
__global__ __launch_bounds__(256) void nms_kernel(const float* __restrict__ labels) {
    const int bc = blockIdx.x;
    const int b  = bc / CC;
    const int c  = bc % CC;
    const int t  = threadIdx.x;

    __shared__ unsigned long long sk[512];
    __shared__ float4             sbox[KCAND];
    __shared__ float              sscore[KCAND];
    __shared__ int                hist[1024];      // fallback only
    __shared__ int                s_cut, s_count;  // fallback only

    const int cnt = g_cnt[bc];

    if (cnt >= KCAND && cnt <= CAP) {
        // Fast path: candidate list is a superset of the exact top-200
        const unsigned long long* Cl = g_cand + (size_t)bc * CAP;
        for (int i = t; i < 512; i += 256)
            sk[i] = (i < cnt) ? Cl[i] : 0ULL;
    } else {
        // Exact fallback (statistically never taken for this input)
        for (int i = t; i < 1024; i += 256) hist[i] = 0;
        if (t == 0) s_count = 0;
        __syncthreads();

        const float*         Lcol = labels + (size_t)b * NN * CC + c;
        const unsigned char* Mb   = g_mask + (size_t)b * NN;

        for (int n = t; n < NN; n += 256) {
            if (Mb[n]) {
                float s = Lcol[(size_t)n * CC];
                if (s > 0.0f)
                    atomicAdd(&hist[min((int)(s * 1024.0f), 1023)], 1);
            }
        }
        __syncthreads();
        if (t == 0) {
            int cum = 0, cut = 0;
            for (int bin = 1023; bin >= 0; bin--) {
                cum += hist[bin];
                if (cum >= KCAND) { cut = bin; break; }
            }
            s_cut = cut;
        }
        __syncthreads();
        const int fcut = s_cut;
        for (int n = t; n < NN; n += 256) {
            if (Mb[n]) {
                float s = Lcol[(size_t)n * CC];
                if (s > 0.0f && min((int)(s * 1024.0f), 1023) >= fcut) {
                    int p = atomicAdd(&s_count, 1);
                    if (p < 512)
                        sk[p] = ((unsigned long long)__float_as_uint(s) << 32)
                                | (unsigned)(~(unsigned)n);
                }
            }
        }
        __syncthreads();
        const int M = min(s_count, 512);
        for (int i = M + t; i < 512; i += 256) sk[i] = 0ULL;
    }
    __syncthreads();

    sort512_desc(sk, t);
    __syncthreads();

    // Expand top-200 into score/box smem
    if (t < KCAND) {
        unsigned long long kk = sk[t];
        float s = __uint_as_float((unsigned)(kk >> 32));
        sscore[t] = s;
        float4 bx = make_float4(0.f, 0.f, 0.f, 0.f);
        if (s > 0.0f) bx = g_boxes[(size_t)b * NN + (~(unsigned)kk)];
        sbox[t] = bx;
    }
    __syncthreads();

    // Single-warp greedy NMS: boxes in smem, suppression bits in registers.
    if (t < 32) {
        const int lane    = t;
        const int outbase = bc * MAXPC;
        unsigned  sup     = 0;
        int       kc      = 0;
        for (int i = 0; i < KCAND; i++) {
            float si = sscore[i];
            if (si <= 0.5f) break;                        // sorted: later <=
            unsigned om = __shfl_sync(FULLM, sup, i & 31);
            if ((om >> (i >> 5)) & 1) continue;           // suppressed
            if (lane == 0) {
                g_cls_scores[outbase + kc] = si;
                g_cls_boxes[outbase + kc]  = sbox[i];
            }
            kc++;
            if (kc >= MAXPC) break;                       // first-20 complete
            float4 bi = sbox[i];
#pragma unroll
            for (int m = 0; m < 7; m++) {
                int idx = lane + 32 * m;
                if (idx > i && idx < KCAND && !((sup >> m) & 1)) {
                    if (iou_f(bi, sbox[idx]) > 0.5f) sup |= (1u << m);
                }
            }
        }
        if (lane < MAXPC && lane >= kc) {
            g_cls_scores[outbase + lane] = 0.0f;
            g_cls_boxes[outbase + lane]  = make_float4(0.f, 0.f, 0.f, 0.f);
        }
    }
}

// ---------------------------------------------------------------------------
// Kernel C: per-batch merge of 21*20 = 420 entries -> top-20 overall
// ---------------------------------------------------------------------------
__global__ __launch_bounds__(256) void merge_kernel(float* __restrict__ out) {
    const int b = blockIdx.x;
    const int t = threadIdx.x;
    __shared__ unsigned long long sk[512];

    for (int i = t; i < 512; i += 256) {
        unsigned long long kk = 0ULL;
        if (i < CC * MAXPC) {
            float s = g_cls_scores[b * CC * MAXPC + i];
            kk = ((unsigned long long)__float_as_uint(s) << 32)
                 | (unsigned)(~(unsigned)i);
        }
        sk[i] = kk;
    }
    __syncthreads();

    sort512_desc(sk, t);
    __syncthreads();

    if (t < MAXTOT) {
        unsigned long long kk = sk[t];
        float s   = __uint_as_float((unsigned)(kk >> 32));
        float4 bx = make_float4(0.f, 0.f, 0.f, 0.f);
        float lab = 0.0f;
        if (s > 0.0f) {
            unsigned fi = ~(unsigned)kk;   // flat index in [0, 420)
            bx = g_cls_boxes[b * CC * MAXPC + fi];
            bx.x = fminf(fmaxf(bx.x, 0.0f), 1.0f);
            bx.y = fminf(fmaxf(bx.y, 0.0f), 1.0f);
            bx.z = fminf(fmaxf(bx.z, 0.0f), 1.0f);
            bx.w = fminf(fmaxf(bx.w, 0.0f), 1.0f);
            lab = (float)(fi / MAXPC);
        }
        // Output layout: boxes [B,20,4] | vals [B,20] | labels [B,20]
        float* ob = out + (size_t)b * MAXTOT * 4;
        float* ov = out + (size_t)BB * MAXTOT * 4 + (size_t)b * MAXTOT;
        float* ol = out + (size_t)BB * MAXTOT * 4 + (size_t)BB * MAXTOT
                        + (size_t)b * MAXTOT;
        ob[t * 4 + 0] = bx.x;
        ob[t * 4 + 1] = bx.y;
        ob[t * 4 + 2] = bx.z;
        ob[t * 4 + 3] = bx.w;
        ov[t] = s;
        ol[t] = lab;
    }
}

// ---------------------------------------------------------------------------
extern "C" void kernel_launch(void* const* d_in, const int* in_sizes, int n_in,
                              void* d_out, int out_size) {
    const float* deltas  = (const float*)d_in[0];  // (64, 8732, 4)
    const float* labels  = (const float*)d_in[1];  // (64, 8732, 21)
    const float* anchors = (const float*)d_in[2];  // (8732, 4)
    float* out = (float*)d_out;

    init_kernel<<<(BB * CC + 255) / 256, 256>>>();
    decode_kernel<<<(BB * NN + 255) / 256, 256>>>(deltas, labels, anchors);
    nms_kernel<<<BB * CC, 256>>>(labels);
    merge_kernel<<<BB, 256>>>(out);
}

// round 7
// speedup vs baseline: 1.7498x; 1.7498x over previous
#include <cuda_runtime.h>
#include <math.h>

// Problem constants
#define BB 64
#define NN 8732
#define NN4 (NN / 4)            // 2183
#define CC 21
#define KCAND 200
#define MAXPC 20
#define MAXTOT 20

#define TH_C  0.96f             // collect threshold, classes >= 1
#define TH_0  0.92f             // collect threshold, class 0

#define TILE 128
#define NTILES ((NN + TILE - 1) / TILE)   // 69
#define SLP 129                           // padded smem pitch

// Scratch (static device globals: allowed; no runtime allocation)
__device__ float4 g_boxes[BB * NN];                  // decoded boxes
__device__ float4 g_scoresT4[(size_t)BB * CC * NN4]; // masked scores, [b][c][n/4]
__device__ float  g_cls_scores[BB * CC * MAXPC];
__device__ float4 g_cls_boxes[BB * CC * MAXPC];

// ---------------------------------------------------------------------------
// Kernel A (identical to the R4-measured 23.6us version): decode boxes +
// argmax mask + transposed masked-score write. 128 threads / 128 anchors.
// ---------------------------------------------------------------------------
__global__ __launch_bounds__(TILE) void decode_kernel(
        const float* __restrict__ deltas,
        const float* __restrict__ labels,
        const float* __restrict__ anchors) {
    const int b    = blockIdx.x / NTILES;
    const int tile = blockIdx.x % NTILES;
    const int n0   = tile * TILE;
    const int cnt  = min(TILE, NN - n0);        // 128 or 28; always mult of 4
    const int t    = threadIdx.x;

    __shared__ float         sl[CC * SLP];      // [class][anchor], padded
    __shared__ unsigned char sm[TILE];

    // Coalesced global read, class-major smem write
    const float* Lb  = labels + ((size_t)b * NN + n0) * CC;
    const int    tot = cnt * CC;
    for (int idx = t; idx < tot; idx += TILE) {
        int i = idx / CC;
        int c = idx - i * CC;
        sl[c * SLP + i] = Lb[idx];
    }
    __syncthreads();

    if (t < cnt) {
        // argmax over 21 classes (first-occurrence ties, like jnp.argmax)
        float best = sl[t];
        int   bi   = 0;
#pragma unroll
        for (int c = 1; c < CC; c++) {
            float v = sl[c * SLP + t];
            if (v > best) { best = v; bi = c; }
        }
        sm[t] = (bi != 0) ? 1 : 0;

        // decode box
        const int n = n0 + t;
        float4 a = __ldg(((const float4*)anchors) + n);
        float4 d = __ldg(((const float4*)deltas) + (size_t)b * NN + n);
        d.x *= 0.1f; d.y *= 0.1f; d.z *= 0.2f; d.w *= 0.2f;

        float ah  = a.z - a.x;
        float aw  = a.w - a.y;
        float acy = a.x + 0.5f * ah;
        float acx = a.y + 0.5f * aw;
        float cy  = d.x * ah + acy;
        float cx  = d.y * aw + acx;
        float h   = expf(d.z) * ah;
        float w   = expf(d.w) * aw;

        g_boxes[(size_t)b * NN + n] = make_float4(cy - 0.5f * h, cx - 0.5f * w,
                                                  cy + 0.5f * h, cx + 0.5f * w);
    }
    __syncthreads();

    // Transposed masked-score write, float4 per (class, anchor-quad)
    const int g4 = cnt >> 2;
    for (int idx = t; idx < CC * g4; idx += TILE) {
        const int c  = idx / g4;
        const int i4 = idx - c * g4;
        float4 v;
        const int ib = i4 * 4;
        v.x = sm[ib + 0] ? sl[c * SLP + ib + 0] : 0.0f;
        v.y = sm[ib + 1] ? sl[c * SLP + ib + 1] : 0.0f;
        v.z = sm[ib + 2] ? sl[c * SLP + ib + 2] : 0.0f;
        v.w = sm[ib + 3] ? sl[c * SLP + ib + 3] : 0.0f;
        g_scoresT4[((size_t)b * CC + c) * NN4 + (n0 >> 2) + i4] = v;
    }
}

// ---------------------------------------------------------------------------
// IoU, exactly mirroring the reference fp32 formula
// ---------------------------------------------------------------------------
__device__ __forceinline__ float iou_f(float4 A, float4 B2) {
    float areaA = (A.z - A.x) * (A.w - A.y);
    float areaB = (B2.z - B2.x) * (B2.w - B2.y);
    float ih = fminf(A.z, B2.z) - fmaxf(A.x, B2.x); ih = fmaxf(ih, 0.0f);
    float iw = fminf(A.w, B2.w) - fmaxf(A.y, B2.y); iw = fmaxf(iw, 0.0f);
    float inter = ih * iw;
    return inter / (areaA + areaB - inter + 1e-8f);
}

// ---------------------------------------------------------------------------
// Kernel B: per-(b,c) top-200 + NMS. Fast path: SINGLE streaming pass
// collecting scores >= th (provable top-200 superset when 200<=cnt<=512).
// Sort and serial NMS are byte-identical to the R3-measured versions.
// ---------------------------------------------------------------------------
__global__ __launch_bounds__(256) void nms_kernel() {
    const int b   = blockIdx.x / CC;
    const int c   = blockIdx.x % CC;
    const int tid = threadIdx.x;

    __shared__ unsigned long long keys[512];
    __shared__ float4             sbox[KCAND];
    __shared__ float              sscore[KCAND];
    __shared__ unsigned char      ssup[KCAND];
    __shared__ int                hist[1024];            // fallback only
    __shared__ int                s_count, s_cut, s_kc, s_brk;

    if (tid == 0) { s_count = 0; s_kc = 0; s_brk = 0; }
    __syncthreads();

    const float4* S4 = (const float4*)(g_scoresT4 + ((size_t)b * CC + c) * NN4);
    const float   th = (c == 0) ? TH_0 : TH_C;

    // Single streaming pass: collect all scores >= th
    for (int i = tid; i < NN4; i += 256) {
        float4 v = S4[i];
        float ss[4] = { v.x, v.y, v.z, v.w };
#pragma unroll
        for (int k = 0; k < 4; k++) {
            float s = ss[k];
            if (s >= th) {
                int p = atomicAdd(&s_count, 1);
                if (p < 512) {
                    unsigned n = (unsigned)(i * 4 + k);
                    keys[p] = ((unsigned long long)__float_as_uint(s) << 32)
                              | (unsigned)(~n);
                }
            }
        }
    }
    __syncthreads();
    int cnt = s_count;

    if (cnt < KCAND || cnt > 512) {
        // Exact fallback (statistically never taken): histogram two-pass
        for (int i = tid; i < 1024; i += 256) hist[i] = 0;
        if (tid == 0) s_count = 0;
        __syncthreads();
        for (int i = tid; i < NN4; i += 256) {
            float4 v = S4[i];
            float ss[4] = { v.x, v.y, v.z, v.w };
#pragma unroll
            for (int k = 0; k < 4; k++) {
                float s = ss[k];
                if (s > 0.0f)
                    atomicAdd(&hist[min((int)(s * 1024.0f), 1023)], 1);
            }
        }
        __syncthreads();
        if (tid == 0) {
            int cum = 0, cut = 0;
            for (int bin = 1023; bin >= 0; bin--) {
                cum += hist[bin];
                if (cum >= KCAND) { cut = bin; break; }
            }
            s_cut = cut;
        }
        __syncthreads();
        const int fcut = s_cut;
        for (int i = tid; i < NN4; i += 256) {
            float4 v = S4[i];
            float ss[4] = { v.x, v.y, v.z, v.w };
#pragma unroll
            for (int k = 0; k < 4; k++) {
                float s = ss[k];
                if (s > 0.0f && min((int)(s * 1024.0f), 1023) >= fcut) {
                    int p = atomicAdd(&s_count, 1);
                    if (p < 512) {
                        unsigned n = (unsigned)(i * 4 + k);
                        keys[p] = ((unsigned long long)__float_as_uint(s) << 32)
                                  | (unsigned)(~n);
                    }
                }
            }
        }
        __syncthreads();
        cnt = s_count;
    }

    const int M = min(cnt, 512);
    for (int i = M + tid; i < 512; i += 256) keys[i] = 0ULL;
    __syncthreads();

    // Bitonic sort 512 keys descending (R3-measured smem version)
    for (int k = 2; k <= 512; k <<= 1) {
        for (int j = k >> 1; j > 0; j >>= 1) {
            for (int i = tid; i < 512; i += 256) {
                int ixj = i ^ j;
                if (ixj > i) {
                    unsigned long long A = keys[i], Bk = keys[ixj];
                    bool descBlock = ((i & k) == 0);
                    if (descBlock ? (A < Bk) : (A > Bk)) {
                        keys[i] = Bk; keys[ixj] = A;
                    }
                }
            }
            __syncthreads();
        }
    }

    // Expand top-200 into score/box smem
    if (tid < KCAND) {
        unsigned long long kk = keys[tid];
        float s = __uint_as_float((unsigned)(kk >> 32));
        sscore[tid] = s;
        ssup[tid]   = 0;
        float4 bx = make_float4(0.f, 0.f, 0.f, 0.f);
        if (s > 0.0f) bx = g_boxes[(size_t)b * NN + (~(unsigned)kk)];
        sbox[tid] = bx;
    }
    __syncthreads();

    const int outbase = (b * CC + c) * MAXPC;

    // Serial greedy NMS with early exit after 20 keeps (R3-measured version)
    for (int i = 0; i < KCAND; i++) {
        if (tid == 0) {
            int   kc = s_kc;
            float si = sscore[i];
            if (si <= 0.5f || kc >= MAXPC) {
                s_brk = 1;
            } else if (!ssup[i]) {
                g_cls_scores[outbase + kc] = si;
                g_cls_boxes[outbase + kc]  = sbox[i];
                s_kc  = kc + 1;
                s_brk = 2;
            } else {
                s_brk = 0;
            }
        }
        __syncthreads();
        int st = s_brk;
        if (st == 1) break;
        if (st == 2 && tid > i && tid < KCAND && !ssup[tid]) {
            if (iou_f(sbox[i], sbox[tid]) > 0.5f) ssup[tid] = 1;
        }
        __syncthreads();
    }

    __syncthreads();
    if (tid < MAXPC && tid >= s_kc) {
        g_cls_scores[outbase + tid] = 0.0f;
        g_cls_boxes[outbase + tid]  = make_float4(0.f, 0.f, 0.f, 0.f);
    }
}

// ---------------------------------------------------------------------------
// Kernel C (R3-measured version): per-batch merge of 420 entries -> top-20
// ---------------------------------------------------------------------------
__global__ __launch_bounds__(256) void merge_kernel(float* __restrict__ out) {
    const int b   = blockIdx.x;
    const int tid = threadIdx.x;
    __shared__ unsigned long long keys[512];

    for (int i = tid; i < 512; i += 256) {
        unsigned long long kk = 0ULL;
        if (i < CC * MAXPC) {
            float s = g_cls_scores[b * CC * MAXPC + i];
            kk = ((unsigned long long)__float_as_uint(s) << 32)
                 | (unsigned)(~(unsigned)i);
        }
        keys[i] = kk;
    }
    __syncthreads();

    for (int k = 2; k <= 512; k <<= 1) {
        for (int j = k >> 1; j > 0; j >>= 1) {
            for (int i = tid; i < 512; i += 256) {
                int ixj = i ^ j;
                if (ixj > i) {
                    unsigned long long A = keys[i], Bk = keys[ixj];
                    bool descBlock = ((i & k) == 0);
                    if (descBlock ? (A < Bk) : (A > Bk)) {
                        keys[i] = Bk; keys[ixj] = A;
                    }
                }
            }
            __syncthreads();
        }
    }

    if (tid < MAXTOT) {
        unsigned long long kk = keys[tid];
        float s   = __uint_as_float((unsigned)(kk >> 32));
        float4 bx = make_float4(0.f, 0.f, 0.f, 0.f);
        float lab = 0.0f;
        if (s > 0.0f) {
            unsigned fi = ~(unsigned)kk;   // flat index in [0, 420)
            bx = g_cls_boxes[b * CC * MAXPC + fi];
            bx.x = fminf(fmaxf(bx.x, 0.0f), 1.0f);
            bx.y = fminf(fmaxf(bx.y, 0.0f), 1.0f);
            bx.z = fminf(fmaxf(bx.z, 0.0f), 1.0f);
            bx.w = fminf(fmaxf(bx.w, 0.0f), 1.0f);
            lab = (float)(fi / MAXPC);
        }
        // Output layout: boxes [B,20,4] | vals [B,20] | labels [B,20]
        float* ob = out + (size_t)b * MAXTOT * 4;
        float* ov = out + (size_t)BB * MAXTOT * 4 + (size_t)b * MAXTOT;
        float* ol = out + (size_t)BB * MAXTOT * 4 + (size_t)BB * MAXTOT
                        + (size_t)b * MAXTOT;
        ob[tid * 4 + 0] = bx.x;
        ob[tid * 4 + 1] = bx.y;
        ob[tid * 4 + 2] = bx.z;
        ob[tid * 4 + 3] = bx.w;
        ov[tid] = s;
        ol[tid] = lab;
    }
}

// ---------------------------------------------------------------------------
extern "C" void kernel_launch(void* const* d_in, const int* in_sizes, int n_in,
                              void* d_out, int out_size) {
    const float* deltas  = (const float*)d_in[0];  // (64, 8732, 4)
    const float* labels  = (const float*)d_in[1];  // (64, 8732, 21)
    const float* anchors = (const float*)d_in[2];  // (8732, 4)
    float* out = (float*)d_out;

    decode_kernel<<<BB * NTILES, TILE>>>(deltas, labels, anchors);
    nms_kernel<<<BB * CC, 256>>>();
    merge_kernel<<<BB, 256>>>(out);
}

// round 9
// speedup vs baseline: 2.2187x; 1.2680x over previous
#include <cuda_runtime.h>
#include <math.h>

// Problem constants
#define BB 64
#define NN 8732
#define NN4 (NN / 4)            // 2183
#define CC 21
#define KCAND 200
#define MAXPC 20
#define MAXTOT 20
#define FULLM 0xffffffffu

#define TH_C  0.96f             // collect threshold, classes >= 1
#define TH_0  0.92f             // collect threshold, class 0

#define TILE 128
#define NTILES ((NN + TILE - 1) / TILE)   // 69
#define SLP 129                           // padded smem pitch

// Scratch (static device globals: allowed; no runtime allocation)
__device__ float4 g_boxes[BB * NN];                  // decoded boxes
__device__ float4 g_scoresT4[(size_t)BB * CC * NN4]; // masked scores, [b][c][n/4]
__device__ float  g_cls_scores[BB * CC * MAXPC];     // per-class kept, sorted desc
__device__ float4 g_cls_boxes[BB * CC * MAXPC];

// ---------------------------------------------------------------------------
// Kernel A (measured 23.7us): decode + argmax mask + transposed score write
// ---------------------------------------------------------------------------
__global__ __launch_bounds__(TILE) void decode_kernel(
        const float* __restrict__ deltas,
        const float* __restrict__ labels,
        const float* __restrict__ anchors) {
    const int b    = blockIdx.x / NTILES;
    const int tile = blockIdx.x % NTILES;
    const int n0   = tile * TILE;
    const int cnt  = min(TILE, NN - n0);
    const int t    = threadIdx.x;

    __shared__ float         sl[CC * SLP];
    __shared__ unsigned char sm[TILE];

    const float* Lb  = labels + ((size_t)b * NN + n0) * CC;
    const int    tot = cnt * CC;
    for (int idx = t; idx < tot; idx += TILE) {
        int i = idx / CC;
        int c = idx - i * CC;
        sl[c * SLP + i] = Lb[idx];
    }
    __syncthreads();

    if (t < cnt) {
        float best = sl[t];
        int   bi   = 0;
#pragma unroll
        for (int c = 1; c < CC; c++) {
            float v = sl[c * SLP + t];
            if (v > best) { best = v; bi = c; }
        }
        sm[t] = (bi != 0) ? 1 : 0;

        const int n = n0 + t;
        float4 a = __ldg(((const float4*)anchors) + n);
        float4 d = __ldg(((const float4*)deltas) + (size_t)b * NN + n);
        d.x *= 0.1f; d.y *= 0.1f; d.z *= 0.2f; d.w *= 0.2f;

        float ah  = a.z - a.x;
        float aw  = a.w - a.y;
        float acy = a.x + 0.5f * ah;
        float acx = a.y + 0.5f * aw;
        float cy  = d.x * ah + acy;
        float cx  = d.y * aw + acx;
        float h   = expf(d.z) * ah;
        float w   = expf(d.w) * aw;

        g_boxes[(size_t)b * NN + n] = make_float4(cy - 0.5f * h, cx - 0.5f * w,
                                                  cy + 0.5f * h, cx + 0.5f * w);
    }
    __syncthreads();

    const int g4 = cnt >> 2;
    for (int idx = t; idx < CC * g4; idx += TILE) {
        const int c  = idx / g4;
        const int i4 = idx - c * g4;
        float4 v;
        const int ib = i4 * 4;
        v.x = sm[ib + 0] ? sl[c * SLP + ib + 0] : 0.0f;
        v.y = sm[ib + 1] ? sl[c * SLP + ib + 1] : 0.0f;
        v.z = sm[ib + 2] ? sl[c * SLP + ib + 2] : 0.0f;
        v.w = sm[ib + 3] ? sl[c * SLP + ib + 3] : 0.0f;
        g_scoresT4[((size_t)b * CC + c) * NN4 + (n0 >> 2) + i4] = v;
    }
}

// ---------------------------------------------------------------------------
// IoU, exactly mirroring the reference fp32 formula
// ---------------------------------------------------------------------------
__device__ __forceinline__ float iou_f(float4 A, float4 B2) {
    float areaA = (A.z - A.x) * (A.w - A.y);
    float areaB = (B2.z - B2.x) * (B2.w - B2.y);
    float ih = fminf(A.z, B2.z) - fmaxf(A.x, B2.x); ih = fmaxf(ih, 0.0f);
    float iw = fminf(A.w, B2.w) - fmaxf(A.y, B2.y); iw = fmaxf(iw, 0.0f);
    float inter = ih * iw;
    return inter / (areaA + areaB - inter + 1e-8f);
}

// key pack: [score bits:32 | (16383-n):14 | slot:9]  (desc sort => score desc,
// n asc on ties, exact jax top_k stable order; slot survives sorting)
__device__ __forceinline__ unsigned long long pack_key(float s, unsigned n,
                                                       unsigned slot) {
    return ((unsigned long long)__float_as_uint(s) << 32)
         | ((unsigned long long)((16383u - n) & 0x3FFFu) << 9)
         | (unsigned long long)(slot & 0x1FFu);
}

// Warp-register bitonic sort of 32 u64 keys, descending; no barriers.
__device__ __forceinline__ unsigned long long warpsort32_desc(
        unsigned long long key, int lane) {
#pragma unroll
    for (int k = 2; k <= 32; k <<= 1) {
#pragma unroll
        for (int j = k >> 1; j >= 1; j >>= 1) {
            unsigned long long other = __shfl_xor_sync(FULLM, key, j);
            bool dd   = ((lane & k) == 0);
            bool low  = ((lane & j) == 0);
            bool wmax = (dd == low);
            key = wmax ? (key > other ? key : other)
                       : (key < other ? key : other);
        }
    }
    return key;
}

// ---------------------------------------------------------------------------
// Kernel B: per-(b,c): threshold-collect -> 16 warp sorts (sorted runs) ->
// single-warp 16-way merge-pop fused with greedy NMS. 512 threads per block.
// ---------------------------------------------------------------------------
__global__ __launch_bounds__(512) void nms_kernel() {
    const int bc   = blockIdx.x;
    const int b    = bc / CC;
    const int c    = bc % CC;
    const int tid  = threadIdx.x;
    const int lane = tid & 31;
    const int wid  = tid >> 5;

    __shared__ unsigned long long sk[512];
    __shared__ float4             sbox[512];
    __shared__ int                hist[1024];     // fallback only
    __shared__ int                s_count, s_cut;

    if (tid == 0) s_count = 0;
    __syncthreads();

    const float4* S4 = (const float4*)(g_scoresT4 + ((size_t)b * CC + c) * NN4);
    const float   th = (c == 0) ? TH_0 : TH_C;

    // Single streaming pass: collect all scores >= th
    for (int i = tid; i < NN4; i += 512) {
        float4 v = S4[i];
        float ss[4] = { v.x, v.y, v.z, v.w };
#pragma unroll
        for (int k = 0; k < 4; k++) {
            float s = ss[k];
            if (s >= th) {
                int p = atomicAdd(&s_count, 1);
                if (p < 512) sk[p] = pack_key(s, (unsigned)(i * 4 + k),
                                              (unsigned)p);
            }
        }
    }
    __syncthreads();
    int cnt = s_count;

    if (cnt < KCAND || cnt > 512) {
        // Exact fallback (statistically never taken): histogram two-pass
        for (int i = tid; i < 1024; i += 512) hist[i] = 0;
        if (tid == 0) s_count = 0;
        __syncthreads();
        for (int i = tid; i < NN4; i += 512) {
            float4 v = S4[i];
            float ss[4] = { v.x, v.y, v.z, v.w };
#pragma unroll
            for (int k = 0; k < 4; k++) {
                float s = ss[k];
                if (s > 0.0f)
                    atomicAdd(&hist[min((int)(s * 1024.0f), 1023)], 1);
            }
        }
        __syncthreads();
        if (tid == 0) {
            int cum = 0, cut = 0;
            for (int bin = 1023; bin >= 0; bin--) {
                cum += hist[bin];
                if (cum >= KCAND) { cut = bin; break; }
            }
            s_cut = cut;
        }
        __syncthreads();
        const int fcut = s_cut;
        for (int i = tid; i < NN4; i += 512) {
            float4 v = S4[i];
            float ss[4] = { v.x, v.y, v.z, v.w };
#pragma unroll
            for (int k = 0; k < 4; k++) {
                float s = ss[k];
                if (s > 0.0f && min((int)(s * 1024.0f), 1023) >= fcut) {
                    int p = atomicAdd(&s_count, 1);
                    if (p < 512) sk[p] = pack_key(s, (unsigned)(i * 4 + k),
                                                  (unsigned)p);
                }
            }
        }
        __syncthreads();
        cnt = s_count;
    }

    const int mn = min(cnt, 512);
    if (tid >= mn) sk[tid] = 0ULL;
    __syncthreads();

    // Prefetch boxes (slot-indexed; overlaps with the register sort below)
    unsigned long long key = sk[tid];
    if (tid < mn) {
        unsigned n = 16383u - (unsigned)((key >> 9) & 0x3FFFu);
        sbox[tid] = g_boxes[(size_t)b * NN + n];
    }
    // 16 independent sorted runs of 32, zero block barriers
    key = warpsort32_desc(key, lane);
    sk[tid] = key;
    __syncthreads();

    // Warp 0: 16-way merge-pop fused with greedy NMS (exact top-200 order)
    if (wid == 0) {
        const int outbase = bc * MAXPC;
        int    head   = 0;
        int    kc     = 0;
        int    pops   = 0;
        const int maxpops = min(mn, KCAND);
        float4 mykept = make_float4(0.f, 0.f, 0.f, 0.f);

        while (pops < maxpops && kc < MAXPC) {
            unsigned long long hk = 0ULL;
            if (lane < 16 && head < 32) hk = sk[lane * 32 + head];
            // butterfly argmax (keys unique; 0 = exhausted)
            unsigned long long bk = hk;
            int bl = lane;
#pragma unroll
            for (int off = 16; off >= 1; off >>= 1) {
                unsigned long long ok = __shfl_xor_sync(FULLM, bk, off);
                int                ol = __shfl_xor_sync(FULLM, bl, off);
                if (ok > bk) { bk = ok; bl = ol; }
            }
            if (bk == 0ULL) break;
            if (lane == bl) head++;
            pops++;

            float s = __uint_as_float((unsigned)(bk >> 32));
            if (s <= 0.5f) break;               // sorted: all later smaller
            int slot = (int)(bk & 0x1FFu);
            float4 cb = sbox[slot];             // smem broadcast

            bool ov = (lane < kc) && (iou_f(mykept, cb) > 0.5f);
            if (!__ballot_sync(FULLM, ov)) {
                if (lane == kc) mykept = cb;
                if (lane == 0) {
                    g_cls_scores[outbase + kc] = s;
                    g_cls_boxes[outbase + kc]  = cb;
                }
                kc++;
            }
        }
        if (lane < MAXPC && lane >= kc) {
            g_cls_scores[outbase + lane] = 0.0f;
            g_cls_boxes[outbase + lane]  = make_float4(0.f, 0.f, 0.f, 0.f);
        }
    }
}

// ---------------------------------------------------------------------------
// Kernel C: per-batch top-20 via 21-way merge-pop of the already-sorted
// per-class lists. One warp per batch; 8 warps per block.
// ---------------------------------------------------------------------------
__global__ __launch_bounds__(256) void merge_kernel(float* __restrict__ out) {
    const int wid  = threadIdx.x >> 5;
    const int lane = threadIdx.x & 31;
    const int b    = blockIdx.x * 8 + wid;

    __shared__ float ssc[8][CC * MAXPC];

    for (int i = lane; i < CC * MAXPC; i += 32)
        ssc[wid][i] = g_cls_scores[b * CC * MAXPC + i];
    __syncwarp();

    int   head  = 0;
    int   myfi  = 0;
    float myval = 0.0f;
    bool  mywin = false;

#pragma unroll
    for (int p = 0; p < MAXTOT; p++) {
        // key: [score bits:32 | (1023-flat):16]; desc => score desc, flat asc
        unsigned long long k = 0ULL;
        if (lane < CC && head < MAXPC) {
            int   fi = lane * MAXPC + head;
            float s  = ssc[wid][fi];
            k = ((unsigned long long)__float_as_uint(s) << 16)
                | (unsigned long long)(1023 - fi);
        }
        unsigned long long bk = k;
#pragma unroll
        for (int off = 16; off >= 1; off >>= 1) {
            unsigned long long ok = __shfl_xor_sync(FULLM, bk, off);
            if (ok > bk) bk = ok;
        }
        int   fi = 1023 - (int)(bk & 0xFFFFu);
        float s  = __uint_as_float((unsigned)(bk >> 16));   // FIX: >>16, not >>32
        if (lane == fi / MAXPC) head++;         // winner class advances
        if (lane == p) { myfi = fi; myval = s; mywin = true; }
    }

    if (lane < MAXTOT && mywin) {
        float  s  = myval;
        float4 bx = make_float4(0.f, 0.f, 0.f, 0.f);
        float  lab = 0.0f;
        if (s > 0.0f) {
            bx = g_cls_boxes[b * CC * MAXPC + myfi];
            bx.x = fminf(fmaxf(bx.x, 0.0f), 1.0f);
            bx.y = fminf(fmaxf(bx.y, 0.0f), 1.0f);
            bx.z = fminf(fmaxf(bx.z, 0.0f), 1.0f);
            bx.w = fminf(fmaxf(bx.w, 0.0f), 1.0f);
            lab = (float)(myfi / MAXPC);
        }
        // Output layout: boxes [B,20,4] | vals [B,20] | labels [B,20]
        float* ob = out + (size_t)b * MAXTOT * 4;
        float* ov = out + (size_t)BB * MAXTOT * 4 + (size_t)b * MAXTOT;
        float* ol = out + (size_t)BB * MAXTOT * 4 + (size_t)BB * MAXTOT
                        + (size_t)b * MAXTOT;
        ob[lane * 4 + 0] = bx.x;
        ob[lane * 4 + 1] = bx.y;
        ob[lane * 4 + 2] = bx.z;
        ob[lane * 4 + 3] = bx.w;
        ov[lane] = s;
        ol[lane] = lab;
    }
}

// ---------------------------------------------------------------------------
extern "C" void kernel_launch(void* const* d_in, const int* in_sizes, int n_in,
                              void* d_out, int out_size) {
    const float* deltas  = (const float*)d_in[0];  // (64, 8732, 4)
    const float* labels  = (const float*)d_in[1];  // (64, 8732, 21)
    const float* anchors = (const float*)d_in[2];  // (8732, 4)
    float* out = (float*)d_out;

    decode_kernel<<<BB * NTILES, TILE>>>(deltas, labels, anchors);
    nms_kernel<<<BB * CC, 512>>>();
    merge_kernel<<<BB / 8, 256>>>(out);
}